// round 2
// baseline (speedup 1.0000x reference)
#include <cuda_runtime.h>

// Problem constants (fixed by the reference: N=16, C=19, H=W=512)
#define NCLS 19
#define NIMG 16
#define HWPX (512 * 512)          // pixels per image = 262144
#define EPSV 1e-6f

#define NBLK_X 256                // HWPX/4 float4s / 256 threads = 256 blocks
#define NBLK_TOTAL (NBLK_X * NIMG)

// Scratch counters: zero at module load; the last block resets them to zero
// every launch (atomicExch read-and-clear), so every graph replay starts clean.
__device__ unsigned int g_pred [NIMG * NCLS];
__device__ unsigned int g_targ [NIMG * NCLS];
__device__ unsigned int g_inter[NIMG * NCLS];
__device__ unsigned int g_done;   // completion ticket

// ---------------------------------------------------------------------------
// Single fused kernel: per-pixel argmax over C=19 -> per-image histograms
// (shared, flushed with global atomics) -> last arriving block computes the
// weighted mean IoU scalar and clears all scratch for the next replay.
// grid = (256, 16), block = 256, 4 adjacent pixels (one float4/plane) per thread.
// ---------------------------------------------------------------------------
__global__ void __launch_bounds__(256)
miou_fused_kernel(const float* __restrict__ preds,
                  const float* __restrict__ targets,
                  const float* __restrict__ w,
                  float* __restrict__ out) {
    __shared__ unsigned int sp[NCLS];
    __shared__ unsigned int st[NCLS];
    __shared__ unsigned int si[NCLS];
    __shared__ unsigned int s_last;

    const int t = threadIdx.x;
    if (t < NCLS) { sp[t] = 0u; st[t] = 0u; si[t] = 0u; }
    __syncthreads();

    const int n = blockIdx.y;
    const int idx4 = blockIdx.x * blockDim.x + t;   // float4 index in plane

    const float4* __restrict__ p4 =
        (const float4*)(preds   + (size_t)n * NCLS * HWPX);
    const float4* __restrict__ q4 =
        (const float4*)(targets + (size_t)n * NCLS * HWPX);

    float bpv[4], btv[4];
    int   bpi[4], bti[4];
#pragma unroll
    for (int j = 0; j < 4; j++) {
        bpv[j] = -3.4e38f; btv[j] = -3.4e38f; bpi[j] = 0; bti[j] = 0;
    }

#pragma unroll
    for (int c = 0; c < NCLS; c++) {
        const size_t off = (size_t)c * (HWPX / 4) + idx4;
        float4 pv = __ldcs(&p4[off]);   // streaming: no reuse
        float4 tv = __ldcs(&q4[off]);
        float pa[4] = {pv.x, pv.y, pv.z, pv.w};
        float ta[4] = {tv.x, tv.y, tv.z, tv.w};
#pragma unroll
        for (int j = 0; j < 4; j++) {
            if (pa[j] > bpv[j]) { bpv[j] = pa[j]; bpi[j] = c; }  // strict >: first-index argmax
            if (ta[j] > btv[j]) { btv[j] = ta[j]; bti[j] = c; }
        }
    }

#pragma unroll
    for (int j = 0; j < 4; j++) {
        atomicAdd(&sp[bpi[j]], 1u);
        atomicAdd(&st[bti[j]], 1u);
        if (bpi[j] == bti[j]) atomicAdd(&si[bpi[j]], 1u);
    }
    __syncthreads();

    if (t < NCLS) {
        if (sp[t]) atomicAdd(&g_pred [n * NCLS + t], sp[t]);
        if (st[t]) atomicAdd(&g_targ [n * NCLS + t], st[t]);
        if (si[t]) atomicAdd(&g_inter[n * NCLS + t], si[t]);
    }

    // ---- last-block-done finalization ----
    __threadfence();   // order the counter flush before the ticket
    if (t == 0) {
        unsigned int prev = atomicAdd(&g_done, 1u);
        s_last = (prev == NBLK_TOTAL - 1) ? 1u : 0u;
    }
    __syncthreads();
    if (!s_last) return;

    // Last block: read-and-clear counters via atomicExch (L2-coherent),
    // compute sum over 304 (image,class) IoU terms.
    float v = 0.0f;
    for (int i = t; i < NIMG * NCLS; i += 256) {
        const int c = i % NCLS;
        float inter = (float)atomicExch(&g_inter[i], 0u);
        float pc    = (float)atomicExch(&g_pred [i], 0u);
        float tc    = (float)atomicExch(&g_targ [i], 0u);
        float uni   = pc + tc - inter;
        v += (inter + EPSV) / (uni + EPSV) * w[c];
    }

    __shared__ float warp_sums[8];
#pragma unroll
    for (int o = 16; o > 0; o >>= 1)
        v += __shfl_down_sync(0xFFFFFFFFu, v, o);
    if ((t & 31) == 0) warp_sums[t >> 5] = v;
    __syncthreads();
    if (t < 32) {
        float s = (t < 8) ? warp_sums[t] : 0.0f;
#pragma unroll
        for (int o = 4; o > 0; o >>= 1)
            s += __shfl_down_sync(0xFFFFFFFFu, s, o);
        if (t == 0) {
            out[0] = s / (float)(NIMG * NCLS);
            g_done = 0u;   // reset ticket for next replay
        }
    }
}

// ---------------------------------------------------------------------------
extern "C" void kernel_launch(void* const* d_in, const int* in_sizes, int n_in,
                              void* d_out, int out_size) {
    const float* preds   = (const float*)d_in[0];
    const float* targets = (const float*)d_in[1];
    const float* weights = (const float*)d_in[2];
    float* out = (float*)d_out;

    dim3 grid(NBLK_X, NIMG);   // 4096 blocks
    miou_fused_kernel<<<grid, 256>>>(preds, targets, weights, out);
}

// round 9
// speedup vs baseline: 1.0042x; 1.0042x over previous
#include <cuda_runtime.h>

// Problem constants (fixed by the reference: N=16, C=19, H=W=512)
#define NCLS 19
#define NIMG 16
#define HWPX (512 * 512)          // pixels per image = 262144
#define EPSV 1e-6f

// Scratch: per-(image,class) counters. Zero at module load; the finalize
// kernel clears them (atomicExch read-and-reset) so every graph replay
// starts from zeros. No zero-kernel launch needed. No allocations anywhere.
__device__ unsigned int g_pred [NIMG * NCLS];
__device__ unsigned int g_targ [NIMG * NCLS];
__device__ unsigned int g_inter[NIMG * NCLS];

// ---------------------------------------------------------------------------
// Kernel 1: per-pixel argmax over C=19 + per-image histograms.
// grid = (256, 16), block = 256. Each thread owns 4 adjacent pixels (one
// float4 per class plane). Fully unrolled class loop -> ptxas front-batches
// 38 independent float4 LDGs (high MLP; kernel is HBM-bound at ~90% of peak).
// Plain cached loads, no fences (R2 showed gpu-scope fences cost ~10%).
// ---------------------------------------------------------------------------
__global__ void __launch_bounds__(256)
miou_hist_kernel(const float* __restrict__ preds,
                 const float* __restrict__ targets) {
    __shared__ unsigned int sp[NCLS];
    __shared__ unsigned int st[NCLS];
    __shared__ unsigned int si[NCLS];

    const int t = threadIdx.x;
    if (t < NCLS) { sp[t] = 0u; st[t] = 0u; si[t] = 0u; }
    __syncthreads();

    const int n = blockIdx.y;
    const int idx4 = blockIdx.x * blockDim.x + t;   // float4 index in plane

    const float4* __restrict__ p4 =
        (const float4*)(preds   + (size_t)n * NCLS * HWPX);
    const float4* __restrict__ q4 =
        (const float4*)(targets + (size_t)n * NCLS * HWPX);

    float bpv[4], btv[4];
    int   bpi[4], bti[4];
#pragma unroll
    for (int j = 0; j < 4; j++) {
        bpv[j] = -3.4e38f; btv[j] = -3.4e38f; bpi[j] = 0; bti[j] = 0;
    }

#pragma unroll
    for (int c = 0; c < NCLS; c++) {
        const size_t off = (size_t)c * (HWPX / 4) + idx4;
        float4 pv = p4[off];
        float4 tv = q4[off];
        float pa[4] = {pv.x, pv.y, pv.z, pv.w};
        float ta[4] = {tv.x, tv.y, tv.z, tv.w};
#pragma unroll
        for (int j = 0; j < 4; j++) {
            if (pa[j] > bpv[j]) { bpv[j] = pa[j]; bpi[j] = c; }  // strict >: first-index argmax
            if (ta[j] > btv[j]) { btv[j] = ta[j]; bti[j] = c; }
        }
    }

#pragma unroll
    for (int j = 0; j < 4; j++) {
        atomicAdd(&sp[bpi[j]], 1u);
        atomicAdd(&st[bti[j]], 1u);
        if (bpi[j] == bti[j]) atomicAdd(&si[bpi[j]], 1u);
    }
    __syncthreads();

    if (t < NCLS) {
        if (sp[t]) atomicAdd(&g_pred [n * NCLS + t], sp[t]);
        if (st[t]) atomicAdd(&g_targ [n * NCLS + t], st[t]);
        if (si[t]) atomicAdd(&g_inter[n * NCLS + t], si[t]);
    }
}

// ---------------------------------------------------------------------------
// Kernel 2: finalize + clear. One block of 320 threads; each of the 304
// (image,class) terms is read-and-reset with atomicExch so the counters are
// zero again for the next graph replay.
// out = mean_n mean_c ( (inter+eps)/(union+eps) * w[c] ) = sum / (N*C)
// ---------------------------------------------------------------------------
__global__ void __launch_bounds__(320)
miou_final_kernel(const float* __restrict__ w, float* __restrict__ out) {
    const int t = threadIdx.x;
    float v = 0.0f;
    if (t < NIMG * NCLS) {
        const int c = t % NCLS;
        float inter = (float)atomicExch(&g_inter[t], 0u);
        float pc    = (float)atomicExch(&g_pred [t], 0u);
        float tc    = (float)atomicExch(&g_targ [t], 0u);
        float uni   = pc + tc - inter;
        v = (inter + EPSV) / (uni + EPSV) * w[c];
    }

    // block reduction: warp shuffle then shared (10 warps)
    __shared__ float warp_sums[10];
#pragma unroll
    for (int o = 16; o > 0; o >>= 1)
        v += __shfl_down_sync(0xFFFFFFFFu, v, o);
    if ((t & 31) == 0) warp_sums[t >> 5] = v;
    __syncthreads();
    if (t < 32) {
        float s = (t < 10) ? warp_sums[t] : 0.0f;
#pragma unroll
        for (int o = 8; o > 0; o >>= 1)
            s += __shfl_down_sync(0xFFFFFFFFu, s, o);
        if (t == 0) out[0] = s / (float)(NIMG * NCLS);
    }
}

// ---------------------------------------------------------------------------
extern "C" void kernel_launch(void* const* d_in, const int* in_sizes, int n_in,
                              void* d_out, int out_size) {
    const float* preds   = (const float*)d_in[0];
    const float* targets = (const float*)d_in[1];
    const float* weights = (const float*)d_in[2];
    float* out = (float*)d_out;

    dim3 grid(256, NIMG);   // 4096 blocks, 4 pixels/thread
    miou_hist_kernel<<<grid, 256>>>(preds, targets);
    miou_final_kernel<<<1, 320>>>(weights, out);
}